// round 7
// baseline (speedup 1.0000x reference)
#include <cuda_runtime.h>
#include <cstdint>

#define BB 4
#define TT 2048
#define EE 2048
#define DD 128

#define NEG_INF __int_as_float(0xff800000)

// -------- scratch (device globals: allocation-guard safe) --------
__device__ float g_Q[BB * TT * DD];
__device__ float g_K[BB * TT * DD];
__device__ float g_V[BB * TT * DD];
__device__ float g_S[(size_t)BB * TT * TT];   // 64 MB, only tiles with s_tile<=t_tile written
__device__ float g_m[BB * TT];                // per-column max
__device__ float g_r[BB * TT];                // per-column 1/sum(exp)

// ============================================================================
// Kernel 1: Q/K/V projection. C[8192,128] = x[8192,2048] @ W[2048,128]
// BM=64, BN=128, BK=16, 256 threads, 8x4 per-thread tile. grid=(128, 3)
// ============================================================================
__global__ __launch_bounds__(256) void proj_kernel(
    const float* __restrict__ x,
    const float* __restrict__ Wq,
    const float* __restrict__ Wk,
    const float* __restrict__ Wv)
{
    constexpr int BM = 64, BK = 16;
    __shared__ float As[BK][BM];     // transposed x tile
    __shared__ float Bs[BK][DD];

    const float* W = (blockIdx.y == 0) ? Wq : (blockIdx.y == 1) ? Wk : Wv;
    float* out     = (blockIdx.y == 0) ? g_Q : (blockIdx.y == 1) ? g_K : g_V;

    const int m0  = blockIdx.x * BM;
    const int tid = threadIdx.x;
    const int tm  = (tid >> 5) * 8;   // 0..56
    const int tn  = (tid & 31) * 4;   // 0..124

    // A-tile load mapping: 64 rows x 16 cols = 256 float4, 1 per thread
    const int ar  = tid >> 2;         // 0..63
    const int ac  = (tid & 3) * 4;    // 0,4,8,12
    // B-tile load mapping: 16 rows x 128 cols = 512 float4, 2 per thread
    const int br  = tid >> 5;         // 0..7 (and +8)
    const int bc  = (tid & 31) * 4;   // 0..124

    float acc[8][4] = {};

    for (int k0 = 0; k0 < EE; k0 += BK) {
        float4 av  = *(const float4*)(x + (size_t)(m0 + ar) * EE + k0 + ac);
        float4 bv0 = *(const float4*)(W + (size_t)(k0 + br)     * DD + bc);
        float4 bv1 = *(const float4*)(W + (size_t)(k0 + br + 8) * DD + bc);
        __syncthreads();
        As[ac + 0][ar] = av.x; As[ac + 1][ar] = av.y;
        As[ac + 2][ar] = av.z; As[ac + 3][ar] = av.w;
        *(float4*)&Bs[br][bc]     = bv0;
        *(float4*)&Bs[br + 8][bc] = bv1;
        __syncthreads();
        #pragma unroll
        for (int k = 0; k < BK; k++) {
            float a[8], b[4];
            *(float4*)(a)     = *(const float4*)&As[k][tm];
            *(float4*)(a + 4) = *(const float4*)&As[k][tm + 4];
            *(float4*)(b)     = *(const float4*)&Bs[k][tn];
            #pragma unroll
            for (int i = 0; i < 8; i++)
                #pragma unroll
                for (int j = 0; j < 4; j++)
                    acc[i][j] += a[i] * b[j];
        }
    }

    #pragma unroll
    for (int i = 0; i < 8; i++) {
        *(float4*)(out + (size_t)(m0 + tm + i) * DD + tn) =
            make_float4(acc[i][0], acc[i][1], acc[i][2], acc[i][3]);
    }
}

// ============================================================================
// Kernel 2: S[b,t,s] = scale * dot(Q[b,t,:], K[b,s,:]); -inf for s>t
// inside diagonal 128-tiles; upper-triangular 128-tiles skipped entirely.
// BM=BN=128, BK=16, 256 threads, 8x8 per thread. grid=(16,16,4)
// ============================================================================
__global__ __launch_bounds__(256) void score_kernel()
{
    const int bt = blockIdx.x;
    const int bs = blockIdx.y;
    if (bs > bt) return;                 // never computed, never read
    const int b  = blockIdx.z;

    constexpr int BMN = 128, BK = 16;
    __shared__ float Qs[BK][BMN];
    __shared__ float Ks[BK][BMN];

    const float* Q = g_Q + (size_t)b * TT * DD;
    const float* K = g_K + (size_t)b * TT * DD;
    const int t0 = bt * BMN, s0 = bs * BMN;

    const int tid = threadIdx.x;
    const int tm  = (tid >> 4) * 8;
    const int tn  = (tid & 15) * 8;

    // load mapping: 128 rows x 16 cols = 512 float4 -> 2 per thread
    const int lr = tid >> 2;         // 0..63 (and +64)
    const int lc = (tid & 3) * 4;    // 0,4,8,12

    float acc[8][8] = {};

    for (int k0 = 0; k0 < DD; k0 += BK) {
        float4 q0 = *(const float4*)(Q + (size_t)(t0 + lr)      * DD + k0 + lc);
        float4 q1 = *(const float4*)(Q + (size_t)(t0 + lr + 64) * DD + k0 + lc);
        float4 k0v = *(const float4*)(K + (size_t)(s0 + lr)      * DD + k0 + lc);
        float4 k1v = *(const float4*)(K + (size_t)(s0 + lr + 64) * DD + k0 + lc);
        __syncthreads();
        Qs[lc + 0][lr] = q0.x; Qs[lc + 1][lr] = q0.y; Qs[lc + 2][lr] = q0.z; Qs[lc + 3][lr] = q0.w;
        Qs[lc + 0][lr + 64] = q1.x; Qs[lc + 1][lr + 64] = q1.y; Qs[lc + 2][lr + 64] = q1.z; Qs[lc + 3][lr + 64] = q1.w;
        Ks[lc + 0][lr] = k0v.x; Ks[lc + 1][lr] = k0v.y; Ks[lc + 2][lr] = k0v.z; Ks[lc + 3][lr] = k0v.w;
        Ks[lc + 0][lr + 64] = k1v.x; Ks[lc + 1][lr + 64] = k1v.y; Ks[lc + 2][lr + 64] = k1v.z; Ks[lc + 3][lr + 64] = k1v.w;
        __syncthreads();
        #pragma unroll
        for (int k = 0; k < BK; k++) {
            float qa[8], kb[8];
            *(float4*)(qa)     = *(const float4*)&Qs[k][tm];
            *(float4*)(qa + 4) = *(const float4*)&Qs[k][tm + 4];
            *(float4*)(kb)     = *(const float4*)&Ks[k][tn];
            *(float4*)(kb + 4) = *(const float4*)&Ks[k][tn + 4];
            #pragma unroll
            for (int i = 0; i < 8; i++)
                #pragma unroll
                for (int j = 0; j < 8; j++)
                    acc[i][j] += qa[i] * kb[j];
        }
    }

    const float scale = 0.08838834764831845f;   // 1/sqrt(128)
    float* Sb = g_S + (size_t)b * TT * TT;
    #pragma unroll
    for (int i = 0; i < 8; i++) {
        const int t = t0 + tm + i;
        float v[8];
        #pragma unroll
        for (int j = 0; j < 8; j++) {
            const int s = s0 + tn + j;
            v[j] = (s > t) ? NEG_INF : acc[i][j] * scale;
        }
        *(float4*)(Sb + (size_t)t * TT + s0 + tn)     = make_float4(v[0], v[1], v[2], v[3]);
        *(float4*)(Sb + (size_t)t * TT + s0 + tn + 4) = make_float4(v[4], v[5], v[6], v[7]);
    }
}

// ============================================================================
// Kernel 3: per-column softmax stats over query axis.
// Column s: m = max_{t in [s0,T)} S[t,s], l = sum exp(S-m). Block covers one
// 128-aligned column tile so every read address lies in a written S tile;
// -inf entries (t<s, diagonal tile) contribute exp(-inf)=0 and don't hurt max.
// grid=(16,4), 128 threads
// ============================================================================
__global__ __launch_bounds__(128) void stats_kernel()
{
    const int b  = blockIdx.y;
    const int s0 = blockIdx.x * 128;
    const int s  = s0 + threadIdx.x;
    const float* Sb = g_S + (size_t)b * TT * TT;

    float m = NEG_INF;
    for (int t = s0; t < TT; t++)
        m = fmaxf(m, Sb[(size_t)t * TT + s]);

    float l = 0.0f;
    for (int t = s0; t < TT; t++)
        l += __expf(Sb[(size_t)t * TT + s] - m);   // exp(-inf - m) = 0

    g_m[b * TT + s] = m;
    g_r[b * TT + s] = 1.0f / l;                    // l >= exp(0) = 1 at t=s
}

// ============================================================================
// Kernel 4: Z[b,t,:] = sum_{s<=t} A[t,s] * V[s,:], A = exp(S-m[s]) * r[s]
// computed on the fly during the S-tile load. BM=32 (t), BK=32 (s), BN=128 (d).
// nk = blockIdx.x + 1 triangular k-tile loop. grid=(64,4), 256 threads, 4x4/thr
// ============================================================================
__global__ __launch_bounds__(256) void out_kernel(float* __restrict__ out)
{
    const int b  = blockIdx.y;
    const int t0 = blockIdx.x * 32;

    __shared__ float As[32][32];    // [s_local][t_local]
    __shared__ float Vs[32][DD];

    const float* Sb = g_S + (size_t)b * TT * TT;
    const float* Vb = g_V + (size_t)b * TT * DD;
    const float* mb = g_m + b * TT;
    const float* rb = g_r + b * TT;

    const int tid = threadIdx.x;
    const int tm  = (tid >> 5) * 4;   // 0..28
    const int tn  = (tid & 31) * 4;   // 0..124

    // S-tile load: 32x32 = 256 float4, 1 per thread
    const int sr = tid >> 3;          // 0..31 (t_local)
    const int sc = (tid & 7) * 4;     // 0..28 (s_local)

    float acc[4][4] = {};

    const int nk = blockIdx.x + 1;    // k-tiles s0 = 0..t0, step 32
    for (int kt = 0; kt < nk; kt++) {
        const int s0 = kt * 32;

        float4 sv = *(const float4*)(Sb + (size_t)(t0 + sr) * TT + s0 + sc);
        float a0 = __expf(sv.x - mb[s0 + sc + 0]) * rb[s0 + sc + 0];
        float a1 = __expf(sv.y - mb[s0 + sc + 1]) * rb[s0 + sc + 1];
        float a2 = __expf(sv.z - mb[s0 + sc + 2]) * rb[s0 + sc + 2];
        float a3 = __expf(sv.w - mb[s0 + sc + 3]) * rb[s0 + sc + 3];

        float4 vv[4];
        #pragma unroll
        for (int i = 0; i < 4; i++) {
            const int idx = tid + i * 256;
            const int vr  = idx >> 5;         // 0..31
            const int vc  = (idx & 31) * 4;   // 0..124
            vv[i] = *(const float4*)(Vb + (size_t)(s0 + vr) * DD + vc);
        }

        __syncthreads();
        As[sc + 0][sr] = a0; As[sc + 1][sr] = a1;
        As[sc + 2][sr] = a2; As[sc + 3][sr] = a3;
        #pragma unroll
        for (int i = 0; i < 4; i++) {
            const int idx = tid + i * 256;
            *(float4*)&Vs[idx >> 5][(idx & 31) * 4] = vv[i];
        }
        __syncthreads();

        #pragma unroll
        for (int k = 0; k < 32; k++) {
            float a[4], v[4];
            *(float4*)a = *(const float4*)&As[k][tm];
            *(float4*)v = *(const float4*)&Vs[k][tn];
            #pragma unroll
            for (int i = 0; i < 4; i++)
                #pragma unroll
                for (int j = 0; j < 4; j++)
                    acc[i][j] += a[i] * v[j];
        }
    }

    #pragma unroll
    for (int i = 0; i < 4; i++) {
        *(float4*)(out + (size_t)(b * TT + t0 + tm + i) * DD + tn) =
            make_float4(acc[i][0], acc[i][1], acc[i][2], acc[i][3]);
    }
}

// ============================================================================
extern "C" void kernel_launch(void* const* d_in, const int* in_sizes, int n_in,
                              void* d_out, int out_size)
{
    const float* x  = (const float*)d_in[0];
    const float* Wq = (const float*)d_in[1];
    const float* Wk = (const float*)d_in[2];
    const float* Wv = (const float*)d_in[3];
    float* out = (float*)d_out;

    proj_kernel<<<dim3(BB * TT / 64, 3), 256>>>(x, Wq, Wk, Wv);
    score_kernel<<<dim3(TT / 128, TT / 128, BB), 256>>>();
    stats_kernel<<<dim3(TT / 128, BB), 128>>>();
    out_kernel<<<dim3(TT / 32, BB), 256>>>(out);
}

// round 9
// speedup vs baseline: 1.4882x; 1.4882x over previous
#include <cuda_runtime.h>
#include <cstdint>

#define BB 4
#define TT 2048
#define EE 2048
#define DD 128
#define NEG_INF __int_as_float(0xff800000)
#define PAD 36   // smem row stride (floats): %4==0 for float4, 36%32=4 -> conflict-free frags

// -------- scratch (device globals: allocation-guard safe) --------
__device__ float g_Wt[3][DD][EE];             // W transposed, tf32-rounded
__device__ float g_Q[BB * TT * DD];
__device__ float g_K[BB * TT * DD];
__device__ float g_V[BB * TT * DD];
__device__ float g_S[(size_t)BB * TT * TT];
__device__ float g_m[BB * TT];
__device__ float g_r[BB * TT];

__device__ __forceinline__ float tf32r(float x) {
    uint32_t u;
    asm("cvt.rna.tf32.f32 %0, %1;" : "=r"(u) : "f"(x));
    return __uint_as_float(u);
}

// m16n8k8 tf32 MMA: D = A(16x8,row) * B(8x8,col) + C, fp32 accum. d may alias c.
__device__ __forceinline__ void mma8(float* d, const uint32_t* a, const uint32_t* b) {
    asm volatile(
        "mma.sync.aligned.m16n8k8.row.col.f32.tf32.tf32.f32 "
        "{%0,%1,%2,%3}, {%4,%5,%6,%7}, {%8,%9}, {%0,%1,%2,%3};\n"
        : "+f"(d[0]), "+f"(d[1]), "+f"(d[2]), "+f"(d[3])
        : "r"(a[0]), "r"(a[1]), "r"(a[2]), "r"(a[3]), "r"(b[0]), "r"(b[1]));
}

// ============================================================================
// Kernel 0: transpose + tf32-round W -> Wt[w][d][e]
// ============================================================================
__global__ __launch_bounds__(256) void prep_w(
    const float* __restrict__ Wq, const float* __restrict__ Wk, const float* __restrict__ Wv)
{
    __shared__ float t[32][33];
    const int w  = blockIdx.z;
    const float* W = (w == 0) ? Wq : (w == 1) ? Wk : Wv;
    const int e0 = blockIdx.x * 32, d0 = blockIdx.y * 32;
    const int tx = threadIdx.x & 31, ty = threadIdx.x >> 5;
    for (int i = ty; i < 32; i += 8)
        t[i][tx] = W[(size_t)(e0 + i) * DD + d0 + tx];
    __syncthreads();
    for (int i = ty; i < 32; i += 8)
        g_Wt[w][d0 + i][e0 + tx] = tf32r(t[tx][i]);
}

// ============================================================================
// Kernel 1: projection via mma.sync tf32.
// C[64,128] tile = X[64,2048] @ Wt[128,2048]^T. grid=(128, 3), 256 thr (8 warps,
// 4m x 2n, warp tile 16x64). BK=32.
// ============================================================================
__global__ __launch_bounds__(256) void proj_kernel(const float* __restrict__ x)
{
    __shared__ float Xs[64][PAD];    // [m][k] tf32-rounded
    __shared__ float Ws[128][PAD];   // [n][k] (already rounded)

    const int m0 = blockIdx.x * 64;
    const int w  = blockIdx.y;
    const float* Wt = &g_Wt[w][0][0];
    float* out = (w == 0) ? g_Q : (w == 1) ? g_K : g_V;

    const int tid = threadIdx.x, wid = tid >> 5, lane = tid & 31;
    const int g = lane >> 2, tg = lane & 3;
    const int wm = (wid & 3) * 16;
    const int wn = (wid >> 2) * 64;

    float acc[8][4] = {};

    for (int k0 = 0; k0 < EE; k0 += 32) {
        __syncthreads();
        #pragma unroll
        for (int j = 0; j < 2; j++) {
            const int idx = tid + j * 256;
            const int r = idx >> 3, c = (idx & 7) * 4;
            float4 v = *(const float4*)(x + (size_t)(m0 + r) * EE + k0 + c);
            v.x = tf32r(v.x); v.y = tf32r(v.y); v.z = tf32r(v.z); v.w = tf32r(v.w);
            *(float4*)&Xs[r][c] = v;
        }
        #pragma unroll
        for (int j = 0; j < 4; j++) {
            const int idx = tid + j * 256;
            const int r = idx >> 3, c = (idx & 7) * 4;
            *(float4*)&Ws[r][c] = *(const float4*)(Wt + (size_t)r * EE + k0 + c);
        }
        __syncthreads();

        #pragma unroll
        for (int ks = 0; ks < 4; ks++) {
            const int kk = ks * 8;
            uint32_t a[4];
            a[0] = __float_as_uint(Xs[wm + g    ][kk + tg    ]);
            a[1] = __float_as_uint(Xs[wm + g + 8][kk + tg    ]);
            a[2] = __float_as_uint(Xs[wm + g    ][kk + tg + 4]);
            a[3] = __float_as_uint(Xs[wm + g + 8][kk + tg + 4]);
            #pragma unroll
            for (int nt = 0; nt < 8; nt++) {
                uint32_t b[2];
                b[0] = __float_as_uint(Ws[wn + nt * 8 + g][kk + tg    ]);
                b[1] = __float_as_uint(Ws[wn + nt * 8 + g][kk + tg + 4]);
                mma8(acc[nt], a, b);
            }
        }
    }

    #pragma unroll
    for (int nt = 0; nt < 8; nt++) {
        const int col = wn + nt * 8 + tg * 2;
        *(float2*)(out + (size_t)(m0 + wm + g    ) * DD + col) = make_float2(acc[nt][0], acc[nt][1]);
        *(float2*)(out + (size_t)(m0 + wm + g + 8) * DD + col) = make_float2(acc[nt][2], acc[nt][3]);
    }
}

// ============================================================================
// Kernel 2: S = scale*QK^T (causal) via mma.sync tf32. 128x128 tiles, lower-tri
// only. 8 warps (4m x 2n), warp tile 32x64. BK=32 over k=128.
// ============================================================================
__global__ __launch_bounds__(256) void score_kernel()
{
    const int bt = blockIdx.x, bs = blockIdx.y;
    if (bs > bt) return;
    const int b = blockIdx.z;

    __shared__ float Qs[128][PAD];
    __shared__ float Ks[128][PAD];

    const float* Q = g_Q + (size_t)b * TT * DD;
    const float* K = g_K + (size_t)b * TT * DD;
    const int t0 = bt * 128, s0 = bs * 128;

    const int tid = threadIdx.x, wid = tid >> 5, lane = tid & 31;
    const int g = lane >> 2, tg = lane & 3;
    const int wm = (wid & 3) * 32;
    const int wn = (wid >> 2) * 64;

    float acc[2][8][4] = {};

    for (int k0 = 0; k0 < DD; k0 += 32) {
        __syncthreads();
        #pragma unroll
        for (int j = 0; j < 4; j++) {
            const int idx = tid + j * 256;
            const int r = idx >> 3, c = (idx & 7) * 4;
            float4 q = *(const float4*)(Q + (size_t)(t0 + r) * DD + k0 + c);
            q.x = tf32r(q.x); q.y = tf32r(q.y); q.z = tf32r(q.z); q.w = tf32r(q.w);
            *(float4*)&Qs[r][c] = q;
            float4 k = *(const float4*)(K + (size_t)(s0 + r) * DD + k0 + c);
            k.x = tf32r(k.x); k.y = tf32r(k.y); k.z = tf32r(k.z); k.w = tf32r(k.w);
            *(float4*)&Ks[r][c] = k;
        }
        __syncthreads();

        #pragma unroll
        for (int ks = 0; ks < 4; ks++) {
            const int kk = ks * 8;
            uint32_t a[2][4];
            #pragma unroll
            for (int mt = 0; mt < 2; mt++) {
                const int rr = wm + mt * 16;
                a[mt][0] = __float_as_uint(Qs[rr + g    ][kk + tg    ]);
                a[mt][1] = __float_as_uint(Qs[rr + g + 8][kk + tg    ]);
                a[mt][2] = __float_as_uint(Qs[rr + g    ][kk + tg + 4]);
                a[mt][3] = __float_as_uint(Qs[rr + g + 8][kk + tg + 4]);
            }
            #pragma unroll
            for (int nt = 0; nt < 8; nt++) {
                uint32_t bfr[2];
                bfr[0] = __float_as_uint(Ks[wn + nt * 8 + g][kk + tg    ]);
                bfr[1] = __float_as_uint(Ks[wn + nt * 8 + g][kk + tg + 4]);
                mma8(acc[0][nt], a[0], bfr);
                mma8(acc[1][nt], a[1], bfr);
            }
        }
    }

    const float scale = 0.08838834764831845f;   // 1/sqrt(128)
    float* Sb = g_S + (size_t)b * TT * TT;
    #pragma unroll
    for (int mt = 0; mt < 2; mt++) {
        #pragma unroll
        for (int nt = 0; nt < 8; nt++) {
            const int t  = t0 + wm + mt * 16 + g;
            const int sc = s0 + wn + nt * 8 + tg * 2;
            float v0 = (sc     > t) ? NEG_INF : acc[mt][nt][0] * scale;
            float v1 = (sc + 1 > t) ? NEG_INF : acc[mt][nt][1] * scale;
            *(float2*)(Sb + (size_t)t * TT + sc) = make_float2(v0, v1);
            const int t2 = t + 8;
            float v2 = (sc     > t2) ? NEG_INF : acc[mt][nt][2] * scale;
            float v3 = (sc + 1 > t2) ? NEG_INF : acc[mt][nt][3] * scale;
            *(float2*)(Sb + (size_t)t2 * TT + sc) = make_float2(v2, v3);
        }
    }
}

// ============================================================================
// Kernel 3: per-column (query-axis) softmax stats
// ============================================================================
__global__ __launch_bounds__(128) void stats_kernel()
{
    const int b  = blockIdx.y;
    const int s0 = blockIdx.x * 128;
    const int s  = s0 + threadIdx.x;
    const float* Sb = g_S + (size_t)b * TT * TT;

    float m = NEG_INF;
    for (int t = s0; t < TT; t++)
        m = fmaxf(m, Sb[(size_t)t * TT + s]);
    float l = 0.0f;
    for (int t = s0; t < TT; t++)
        l += __expf(Sb[(size_t)t * TT + s] - m);

    g_m[b * TT + s] = m;
    g_r[b * TT + s] = 1.0f / l;
}

// ============================================================================
// Kernel 4: Z = A*V, d-dim split for occupancy. BM=32, BK=32, BN=64.
// grid=(64, 4, 2), 256 threads, 2x4 per thread
// ============================================================================
__global__ __launch_bounds__(256) void out_kernel(float* __restrict__ out)
{
    const int b  = blockIdx.y;
    const int t0 = blockIdx.x * 32;
    const int n0 = blockIdx.z * 64;

    __shared__ float As[32][32];
    __shared__ float Vs[32][64];

    const float* Sb = g_S + (size_t)b * TT * TT;
    const float* Vb = g_V + (size_t)b * TT * DD;
    const float* mb = g_m + b * TT;
    const float* rb = g_r + b * TT;

    const int tid = threadIdx.x;
    const int tm = (tid >> 4) * 2;
    const int tn = (tid & 15) * 4;
    const int sr = tid >> 3;
    const int sc = (tid & 7) * 4;

    float acc[2][4] = {};

    const int nk = blockIdx.x + 1;
    for (int kt = 0; kt < nk; kt++) {
        const int s0 = kt * 32;

        float4 sv = *(const float4*)(Sb + (size_t)(t0 + sr) * TT + s0 + sc);
        float a0 = __expf(sv.x - mb[s0 + sc + 0]) * rb[s0 + sc + 0];
        float a1 = __expf(sv.y - mb[s0 + sc + 1]) * rb[s0 + sc + 1];
        float a2 = __expf(sv.z - mb[s0 + sc + 2]) * rb[s0 + sc + 2];
        float a3 = __expf(sv.w - mb[s0 + sc + 3]) * rb[s0 + sc + 3];

        float4 vv[2];
        #pragma unroll
        for (int i = 0; i < 2; i++) {
            const int idx = tid + i * 256;
            vv[i] = *(const float4*)(Vb + (size_t)(s0 + (idx >> 4)) * DD + n0 + (idx & 15) * 4);
        }

        __syncthreads();
        As[sc + 0][sr] = a0; As[sc + 1][sr] = a1;
        As[sc + 2][sr] = a2; As[sc + 3][sr] = a3;
        #pragma unroll
        for (int i = 0; i < 2; i++) {
            const int idx = tid + i * 256;
            *(float4*)&Vs[idx >> 4][(idx & 15) * 4] = vv[i];
        }
        __syncthreads();

        #pragma unroll
        for (int k = 0; k < 32; k++) {
            float a[2], v[4];
            a[0] = As[k][tm]; a[1] = As[k][tm + 1];
            *(float4*)v = *(const float4*)&Vs[k][tn];
            #pragma unroll
            for (int i = 0; i < 2; i++)
                #pragma unroll
                for (int j = 0; j < 4; j++)
                    acc[i][j] += a[i] * v[j];
        }
    }

    #pragma unroll
    for (int i = 0; i < 2; i++)
        *(float4*)(out + (size_t)(b * TT + t0 + tm + i) * DD + n0 + tn) =
            make_float4(acc[i][0], acc[i][1], acc[i][2], acc[i][3]);
}

// ============================================================================
extern "C" void kernel_launch(void* const* d_in, const int* in_sizes, int n_in,
                              void* d_out, int out_size)
{
    const float* x  = (const float*)d_in[0];
    const float* Wq = (const float*)d_in[1];
    const float* Wk = (const float*)d_in[2];
    const float* Wv = (const float*)d_in[3];
    float* out = (float*)d_out;

    prep_w<<<dim3(EE / 32, DD / 32, 3), 256>>>(Wq, Wk, Wv);
    proj_kernel<<<dim3(BB * TT / 64, 3), 256>>>(x);
    score_kernel<<<dim3(TT / 128, TT / 128, BB), 256>>>();
    stats_kernel<<<dim3(TT / 128, BB), 128>>>();
    out_kernel<<<dim3(TT / 32, BB, 2), 256>>>(out);
}

// round 10
// speedup vs baseline: 1.9196x; 1.2899x over previous
#include <cuda_runtime.h>
#include <cstdint>

#define BB 4
#define TT 2048
#define EE 2048
#define DD 128
#define NEG_INF __int_as_float(0xff800000)
#define PAD 36   // smem row stride (floats): %4==0 for float4, 36%32=4 -> conflict-free frags

// -------- scratch (device globals: allocation-guard safe) --------
__device__ float g_Wt[3][DD][EE];             // W transposed, tf32-rounded
__device__ float g_Q[BB * TT * DD];
__device__ float g_K[BB * TT * DD];
__device__ float g_V[BB * TT * DD];
__device__ float g_S[(size_t)BB * TT * TT];
__device__ float g_pm[BB * 16 * TT];          // per-tile column max partials
__device__ float g_pl[BB * 16 * TT];          // per-tile column sumexp partials
__device__ float g_m[BB * TT];
__device__ float g_r[BB * TT];

__device__ __forceinline__ float tf32r(float x) {
    uint32_t u;
    asm("cvt.rna.tf32.f32 %0, %1;" : "=r"(u) : "f"(x));
    return __uint_as_float(u);
}

// m16n8k8 tf32 MMA: D = A(16x8,row) * B(8x8,col) + C, fp32 accum.
__device__ __forceinline__ void mma8(float* d, const uint32_t* a, const uint32_t* b) {
    asm volatile(
        "mma.sync.aligned.m16n8k8.row.col.f32.tf32.tf32.f32 "
        "{%0,%1,%2,%3}, {%4,%5,%6,%7}, {%8,%9}, {%0,%1,%2,%3};\n"
        : "+f"(d[0]), "+f"(d[1]), "+f"(d[2]), "+f"(d[3])
        : "r"(a[0]), "r"(a[1]), "r"(a[2]), "r"(a[3]), "r"(b[0]), "r"(b[1]));
}

// ============================================================================
// Kernel 0: transpose + tf32-round W -> Wt[w][d][e]
// ============================================================================
__global__ __launch_bounds__(256) void prep_w(
    const float* __restrict__ Wq, const float* __restrict__ Wk, const float* __restrict__ Wv)
{
    __shared__ float t[32][33];
    const int w  = blockIdx.z;
    const float* W = (w == 0) ? Wq : (w == 1) ? Wk : Wv;
    const int e0 = blockIdx.x * 32, d0 = blockIdx.y * 32;
    const int tx = threadIdx.x & 31, ty = threadIdx.x >> 5;
    for (int i = ty; i < 32; i += 8)
        t[i][tx] = W[(size_t)(e0 + i) * DD + d0 + tx];
    __syncthreads();
    for (int i = ty; i < 32; i += 8)
        g_Wt[w][d0 + i][e0 + tx] = tf32r(t[tx][i]);
}

// ============================================================================
// Kernel 1: projection via mma.sync tf32. C[64,128] = X[64,2048] @ Wt^T
// grid=(128, 3), 256 thr (8 warps, 4m x 2n, warp tile 16x64). BK=32.
// ============================================================================
__global__ __launch_bounds__(256) void proj_kernel(const float* __restrict__ x)
{
    __shared__ float Xs[64][PAD];
    __shared__ float Ws[128][PAD];

    const int m0 = blockIdx.x * 64;
    const int w  = blockIdx.y;
    const float* Wt = &g_Wt[w][0][0];
    float* out = (w == 0) ? g_Q : (w == 1) ? g_K : g_V;

    const int tid = threadIdx.x, wid = tid >> 5, lane = tid & 31;
    const int g = lane >> 2, tg = lane & 3;
    const int wm = (wid & 3) * 16;
    const int wn = (wid >> 2) * 64;

    float acc[8][4] = {};

    for (int k0 = 0; k0 < EE; k0 += 32) {
        __syncthreads();
        #pragma unroll
        for (int j = 0; j < 2; j++) {
            const int idx = tid + j * 256;
            const int r = idx >> 3, c = (idx & 7) * 4;
            float4 v = *(const float4*)(x + (size_t)(m0 + r) * EE + k0 + c);
            v.x = tf32r(v.x); v.y = tf32r(v.y); v.z = tf32r(v.z); v.w = tf32r(v.w);
            *(float4*)&Xs[r][c] = v;
        }
        #pragma unroll
        for (int j = 0; j < 4; j++) {
            const int idx = tid + j * 256;
            const int r = idx >> 3, c = (idx & 7) * 4;
            *(float4*)&Ws[r][c] = *(const float4*)(Wt + (size_t)r * EE + k0 + c);
        }
        __syncthreads();

        #pragma unroll
        for (int ks = 0; ks < 4; ks++) {
            const int kk = ks * 8;
            uint32_t a[4];
            a[0] = __float_as_uint(Xs[wm + g    ][kk + tg    ]);
            a[1] = __float_as_uint(Xs[wm + g + 8][kk + tg    ]);
            a[2] = __float_as_uint(Xs[wm + g    ][kk + tg + 4]);
            a[3] = __float_as_uint(Xs[wm + g + 8][kk + tg + 4]);
            #pragma unroll
            for (int nt = 0; nt < 8; nt++) {
                uint32_t b[2];
                b[0] = __float_as_uint(Ws[wn + nt * 8 + g][kk + tg    ]);
                b[1] = __float_as_uint(Ws[wn + nt * 8 + g][kk + tg + 4]);
                mma8(acc[nt], a, b);
            }
        }
    }

    #pragma unroll
    for (int nt = 0; nt < 8; nt++) {
        const int col = wn + nt * 8 + tg * 2;
        *(float2*)(out + (size_t)(m0 + wm + g    ) * DD + col) = make_float2(acc[nt][0], acc[nt][1]);
        *(float2*)(out + (size_t)(m0 + wm + g + 8) * DD + col) = make_float2(acc[nt][2], acc[nt][3]);
    }
}

// ============================================================================
// Kernel 2: S = scale*QK^T (causal) via mma.sync tf32. 128x128 lower-tri tiles.
// ============================================================================
__global__ __launch_bounds__(256) void score_kernel()
{
    const int bt = blockIdx.x, bs = blockIdx.y;
    if (bs > bt) return;
    const int b = blockIdx.z;

    __shared__ float Qs[128][PAD];
    __shared__ float Ks[128][PAD];

    const float* Q = g_Q + (size_t)b * TT * DD;
    const float* K = g_K + (size_t)b * TT * DD;
    const int t0 = bt * 128, s0 = bs * 128;

    const int tid = threadIdx.x, wid = tid >> 5, lane = tid & 31;
    const int g = lane >> 2, tg = lane & 3;
    const int wm = (wid & 3) * 32;
    const int wn = (wid >> 2) * 64;

    float acc[2][8][4] = {};

    for (int k0 = 0; k0 < DD; k0 += 32) {
        __syncthreads();
        #pragma unroll
        for (int j = 0; j < 4; j++) {
            const int idx = tid + j * 256;
            const int r = idx >> 3, c = (idx & 7) * 4;
            float4 q = *(const float4*)(Q + (size_t)(t0 + r) * DD + k0 + c);
            q.x = tf32r(q.x); q.y = tf32r(q.y); q.z = tf32r(q.z); q.w = tf32r(q.w);
            *(float4*)&Qs[r][c] = q;
            float4 k = *(const float4*)(K + (size_t)(s0 + r) * DD + k0 + c);
            k.x = tf32r(k.x); k.y = tf32r(k.y); k.z = tf32r(k.z); k.w = tf32r(k.w);
            *(float4*)&Ks[r][c] = k;
        }
        __syncthreads();

        #pragma unroll
        for (int ks = 0; ks < 4; ks++) {
            const int kk = ks * 8;
            uint32_t a[2][4];
            #pragma unroll
            for (int mt = 0; mt < 2; mt++) {
                const int rr = wm + mt * 16;
                a[mt][0] = __float_as_uint(Qs[rr + g    ][kk + tg    ]);
                a[mt][1] = __float_as_uint(Qs[rr + g + 8][kk + tg    ]);
                a[mt][2] = __float_as_uint(Qs[rr + g    ][kk + tg + 4]);
                a[mt][3] = __float_as_uint(Qs[rr + g + 8][kk + tg + 4]);
            }
            #pragma unroll
            for (int nt = 0; nt < 8; nt++) {
                uint32_t bfr[2];
                bfr[0] = __float_as_uint(Ks[wn + nt * 8 + g][kk + tg    ]);
                bfr[1] = __float_as_uint(Ks[wn + nt * 8 + g][kk + tg + 4]);
                mma8(acc[0][nt], a[0], bfr);
                mma8(acc[1][nt], a[1], bfr);
            }
        }
    }

    const float scale = 0.08838834764831845f;   // 1/sqrt(128)
    float* Sb = g_S + (size_t)b * TT * TT;
    #pragma unroll
    for (int mt = 0; mt < 2; mt++) {
        #pragma unroll
        for (int nt = 0; nt < 8; nt++) {
            const int t  = t0 + wm + mt * 16 + g;
            const int sc = s0 + wn + nt * 8 + tg * 2;
            float v0 = (sc     > t) ? NEG_INF : acc[mt][nt][0] * scale;
            float v1 = (sc + 1 > t) ? NEG_INF : acc[mt][nt][1] * scale;
            *(float2*)(Sb + (size_t)t * TT + sc) = make_float2(v0, v1);
            const int t2 = t + 8;
            float v2 = (sc     > t2) ? NEG_INF : acc[mt][nt][2] * scale;
            float v3 = (sc + 1 > t2) ? NEG_INF : acc[mt][nt][3] * scale;
            *(float2*)(Sb + (size_t)t2 * TT + sc) = make_float2(v2, v3);
        }
    }
}

// ============================================================================
// Kernel 3a: per-tile column stats partials. One block per 128x128 lower-tri
// S tile: m_p[s] = max_t tile, l_p[s] = sum_t exp(tile - m_p).
// grid=(16 s-tiles, 16 t-tiles, 4), 128 threads.
// ============================================================================
__global__ __launch_bounds__(128) void stats_part()
{
    const int st = blockIdx.x, tt = blockIdx.y;
    if (tt < st) return;
    const int b = blockIdx.z;

    const int s = st * 128 + threadIdx.x;
    const float* col = g_S + (size_t)b * TT * TT + (size_t)(tt * 128) * TT + s;

    float m = NEG_INF;
    #pragma unroll 8
    for (int t = 0; t < 128; t++)
        m = fmaxf(m, col[(size_t)t * TT]);

    float l = 0.0f;
    #pragma unroll 8
    for (int t = 0; t < 128; t++)
        l += __expf(col[(size_t)t * TT] - m);   // exp(-inf - m) = 0; m > -inf (diag t=s)

    const int o = (b * 16 + tt) * TT + s;
    g_pm[o] = m;
    g_pl[o] = l;
}

// ============================================================================
// Kernel 3b: combine partials -> m, 1/l per column. grid=(16,4), 128 threads.
// ============================================================================
__global__ __launch_bounds__(128) void stats_comb()
{
    const int b = blockIdx.y;
    const int s = blockIdx.x * 128 + threadIdx.x;
    const int st = s >> 7;

    float m = NEG_INF;
    #pragma unroll
    for (int tt = 15; tt >= 0; tt--) {
        if (tt < st) break;
        m = fmaxf(m, g_pm[(b * 16 + tt) * TT + s]);
    }
    float l = 0.0f;
    #pragma unroll
    for (int tt = 15; tt >= 0; tt--) {
        if (tt < st) break;
        const int o = (b * 16 + tt) * TT + s;
        l += g_pl[o] * __expf(g_pm[o] - m);
    }

    g_m[b * TT + s] = m;
    g_r[b * TT + s] = 1.0f / l;
}

// ============================================================================
// Kernel 4: Z = A*V. BM=32, BK=32, BN=64; grid=(64, 4, 2), longest-first order.
// ============================================================================
__global__ __launch_bounds__(256) void out_kernel(float* __restrict__ out)
{
    const int b  = blockIdx.y;
    const int bx = gridDim.x - 1 - blockIdx.x;   // schedule heavy tiles first
    const int t0 = bx * 32;
    const int n0 = blockIdx.z * 64;

    __shared__ float As[32][32];
    __shared__ float Vs[32][64];

    const float* Sb = g_S + (size_t)b * TT * TT;
    const float* Vb = g_V + (size_t)b * TT * DD;
    const float* mb = g_m + b * TT;
    const float* rb = g_r + b * TT;

    const int tid = threadIdx.x;
    const int tm = (tid >> 4) * 2;
    const int tn = (tid & 15) * 4;
    const int sr = tid >> 3;
    const int sc = (tid & 7) * 4;

    float acc[2][4] = {};

    const int nk = bx + 1;
    for (int kt = 0; kt < nk; kt++) {
        const int s0 = kt * 32;

        float4 sv = *(const float4*)(Sb + (size_t)(t0 + sr) * TT + s0 + sc);
        float a0 = __expf(sv.x - mb[s0 + sc + 0]) * rb[s0 + sc + 0];
        float a1 = __expf(sv.y - mb[s0 + sc + 1]) * rb[s0 + sc + 1];
        float a2 = __expf(sv.z - mb[s0 + sc + 2]) * rb[s0 + sc + 2];
        float a3 = __expf(sv.w - mb[s0 + sc + 3]) * rb[s0 + sc + 3];

        float4 vv[2];
        #pragma unroll
        for (int i = 0; i < 2; i++) {
            const int idx = tid + i * 256;
            vv[i] = *(const float4*)(Vb + (size_t)(s0 + (idx >> 4)) * DD + n0 + (idx & 15) * 4);
        }

        __syncthreads();
        As[sc + 0][sr] = a0; As[sc + 1][sr] = a1;
        As[sc + 2][sr] = a2; As[sc + 3][sr] = a3;
        #pragma unroll
        for (int i = 0; i < 2; i++) {
            const int idx = tid + i * 256;
            *(float4*)&Vs[idx >> 4][(idx & 15) * 4] = vv[i];
        }
        __syncthreads();

        #pragma unroll
        for (int k = 0; k < 32; k++) {
            float a[2], v[4];
            a[0] = As[k][tm]; a[1] = As[k][tm + 1];
            *(float4*)v = *(const float4*)&Vs[k][tn];
            #pragma unroll
            for (int i = 0; i < 2; i++)
                #pragma unroll
                for (int j = 0; j < 4; j++)
                    acc[i][j] += a[i] * v[j];
        }
    }

    #pragma unroll
    for (int i = 0; i < 2; i++)
        *(float4*)(out + (size_t)(b * TT + t0 + tm + i) * DD + n0 + tn) =
            make_float4(acc[i][0], acc[i][1], acc[i][2], acc[i][3]);
}

// ============================================================================
extern "C" void kernel_launch(void* const* d_in, const int* in_sizes, int n_in,
                              void* d_out, int out_size)
{
    const float* x  = (const float*)d_in[0];
    const float* Wq = (const float*)d_in[1];
    const float* Wk = (const float*)d_in[2];
    const float* Wv = (const float*)d_in[3];
    float* out = (float*)d_out;

    prep_w<<<dim3(EE / 32, DD / 32, 3), 256>>>(Wq, Wk, Wv);
    proj_kernel<<<dim3(BB * TT / 64, 3), 256>>>(x);
    score_kernel<<<dim3(TT / 128, TT / 128, BB), 256>>>();
    stats_part<<<dim3(16, 16, BB), 128>>>();
    stats_comb<<<dim3(16, BB), 128>>>();
    out_kernel<<<dim3(TT / 32, BB, 2), 256>>>(out);
}

// round 11
// speedup vs baseline: 2.7424x; 1.4287x over previous
#include <cuda_runtime.h>
#include <cstdint>

#define BB 4
#define TT 2048
#define EE 2048
#define DD 128
#define NEG_INF __int_as_float(0xff800000)
#define PAD 36   // smem row stride (floats): %4==0 for float4, 36%32=4 -> conflict-free frags

// -------- scratch (device globals: allocation-guard safe) --------
__device__ float g_Wt[3][DD][EE];             // W transposed, tf32-rounded
__device__ float g_Q[BB * TT * DD];
__device__ float g_K[BB * TT * DD];
__device__ float g_Vt[DD][BB * TT];           // V transposed, tf32-rounded
__device__ float g_S[(size_t)BB * TT * TT];
__device__ float g_pm[BB * 16 * TT];          // per-tile column max partials
__device__ float g_pl[BB * 16 * TT];          // per-tile column sumexp partials
__device__ float g_m[BB * TT];
__device__ float g_r[BB * TT];

__device__ __forceinline__ float tf32r(float x) {
    uint32_t u;
    asm("cvt.rna.tf32.f32 %0, %1;" : "=r"(u) : "f"(x));
    return __uint_as_float(u);
}

// m16n8k8 tf32 MMA: D = A(16x8,row) * B(8x8,col) + C, fp32 accum.
__device__ __forceinline__ void mma8(float* d, const uint32_t* a, const uint32_t* b) {
    asm volatile(
        "mma.sync.aligned.m16n8k8.row.col.f32.tf32.tf32.f32 "
        "{%0,%1,%2,%3}, {%4,%5,%6,%7}, {%8,%9}, {%0,%1,%2,%3};\n"
        : "+f"(d[0]), "+f"(d[1]), "+f"(d[2]), "+f"(d[3])
        : "r"(a[0]), "r"(a[1]), "r"(a[2]), "r"(a[3]), "r"(b[0]), "r"(b[1]));
}

// ============================================================================
// Kernel 0: transpose + tf32-round W -> Wt[w][d][e]
// ============================================================================
__global__ __launch_bounds__(256) void prep_w(
    const float* __restrict__ Wq, const float* __restrict__ Wk, const float* __restrict__ Wv)
{
    __shared__ float t[32][33];
    const int w  = blockIdx.z;
    const float* W = (w == 0) ? Wq : (w == 1) ? Wk : Wv;
    const int e0 = blockIdx.x * 32, d0 = blockIdx.y * 32;
    const int tx = threadIdx.x & 31, ty = threadIdx.x >> 5;
    for (int i = ty; i < 32; i += 8)
        t[i][tx] = W[(size_t)(e0 + i) * DD + d0 + tx];
    __syncthreads();
    for (int i = ty; i < 32; i += 8)
        g_Wt[w][d0 + i][e0 + tx] = tf32r(t[tx][i]);
}

// ============================================================================
// Kernel 1: projection via mma.sync tf32 with register prefetch.
// C[64,128] = X[64,2048] @ Wt^T. grid=(128, 3), 256 thr, warp tile 16x64, BK=32.
// V output is written transposed + tf32-rounded into g_Vt.
// ============================================================================
__global__ __launch_bounds__(256) void proj_kernel(const float* __restrict__ x)
{
    __shared__ float Xs[64][PAD];
    __shared__ float Ws[128][PAD];

    const int m0 = blockIdx.x * 64;
    const int w  = blockIdx.y;
    const float* Wt = &g_Wt[w][0][0];

    const int tid = threadIdx.x, wid = tid >> 5, lane = tid & 31;
    const int g = lane >> 2, tg = lane & 3;
    const int wm = (wid & 3) * 16;
    const int wn = (wid >> 2) * 64;

    // load mappings
    const int xr = tid >> 3, xc = (tid & 7) * 4;            // +256 -> second half
    float acc[8][4] = {};
    float4 xv[2], wv[4];

    // preload chunk 0
    #pragma unroll
    for (int j = 0; j < 2; j++)
        xv[j] = *(const float4*)(x + (size_t)(m0 + xr + j * 32) * EE + xc);
    #pragma unroll
    for (int j = 0; j < 4; j++)
        wv[j] = *(const float4*)(Wt + (size_t)(xr + j * 32) * EE + xc);

    for (int i = 0; i < 64; i++) {
        __syncthreads();
        #pragma unroll
        for (int j = 0; j < 2; j++) {
            float4 v = xv[j];
            v.x = tf32r(v.x); v.y = tf32r(v.y); v.z = tf32r(v.z); v.w = tf32r(v.w);
            *(float4*)&Xs[xr + j * 32][xc] = v;
        }
        #pragma unroll
        for (int j = 0; j < 4; j++)
            *(float4*)&Ws[xr + j * 32][xc] = wv[j];
        __syncthreads();

        if (i < 63) {
            const int k0 = (i + 1) * 32;
            #pragma unroll
            for (int j = 0; j < 2; j++)
                xv[j] = *(const float4*)(x + (size_t)(m0 + xr + j * 32) * EE + k0 + xc);
            #pragma unroll
            for (int j = 0; j < 4; j++)
                wv[j] = *(const float4*)(Wt + (size_t)(xr + j * 32) * EE + k0 + xc);
        }

        #pragma unroll
        for (int ks = 0; ks < 4; ks++) {
            const int kk = ks * 8;
            uint32_t a[4];
            a[0] = __float_as_uint(Xs[wm + g    ][kk + tg    ]);
            a[1] = __float_as_uint(Xs[wm + g + 8][kk + tg    ]);
            a[2] = __float_as_uint(Xs[wm + g    ][kk + tg + 4]);
            a[3] = __float_as_uint(Xs[wm + g + 8][kk + tg + 4]);
            #pragma unroll
            for (int nt = 0; nt < 8; nt++) {
                uint32_t b[2];
                b[0] = __float_as_uint(Ws[wn + nt * 8 + g][kk + tg    ]);
                b[1] = __float_as_uint(Ws[wn + nt * 8 + g][kk + tg + 4]);
                mma8(acc[nt], a, b);
            }
        }
    }

    if (w < 2) {
        float* out = (w == 0) ? g_Q : g_K;
        #pragma unroll
        for (int nt = 0; nt < 8; nt++) {
            const int col = wn + nt * 8 + tg * 2;
            *(float2*)(out + (size_t)(m0 + wm + g    ) * DD + col) = make_float2(acc[nt][0], acc[nt][1]);
            *(float2*)(out + (size_t)(m0 + wm + g + 8) * DD + col) = make_float2(acc[nt][2], acc[nt][3]);
        }
    } else {
        // V: transposed + tf32-rounded for the A*V mma B-operand
        #pragma unroll
        for (int nt = 0; nt < 8; nt++) {
            const int col = wn + nt * 8 + tg * 2;
            g_Vt[col    ][m0 + wm + g    ] = tf32r(acc[nt][0]);
            g_Vt[col + 1][m0 + wm + g    ] = tf32r(acc[nt][1]);
            g_Vt[col    ][m0 + wm + g + 8] = tf32r(acc[nt][2]);
            g_Vt[col + 1][m0 + wm + g + 8] = tf32r(acc[nt][3]);
        }
    }
}

// ============================================================================
// Kernel 2: S = scale*QK^T (causal) via mma.sync tf32. 128x128 lower-tri tiles.
// ============================================================================
__global__ __launch_bounds__(256) void score_kernel()
{
    const int bt = blockIdx.x, bs = blockIdx.y;
    if (bs > bt) return;
    const int b = blockIdx.z;

    __shared__ float Qs[128][PAD];
    __shared__ float Ks[128][PAD];

    const float* Q = g_Q + (size_t)b * TT * DD;
    const float* K = g_K + (size_t)b * TT * DD;
    const int t0 = bt * 128, s0 = bs * 128;

    const int tid = threadIdx.x, wid = tid >> 5, lane = tid & 31;
    const int g = lane >> 2, tg = lane & 3;
    const int wm = (wid & 3) * 32;
    const int wn = (wid >> 2) * 64;

    float acc[2][8][4] = {};

    for (int k0 = 0; k0 < DD; k0 += 32) {
        __syncthreads();
        #pragma unroll
        for (int j = 0; j < 4; j++) {
            const int idx = tid + j * 256;
            const int r = idx >> 3, c = (idx & 7) * 4;
            float4 q = *(const float4*)(Q + (size_t)(t0 + r) * DD + k0 + c);
            q.x = tf32r(q.x); q.y = tf32r(q.y); q.z = tf32r(q.z); q.w = tf32r(q.w);
            *(float4*)&Qs[r][c] = q;
            float4 k = *(const float4*)(K + (size_t)(s0 + r) * DD + k0 + c);
            k.x = tf32r(k.x); k.y = tf32r(k.y); k.z = tf32r(k.z); k.w = tf32r(k.w);
            *(float4*)&Ks[r][c] = k;
        }
        __syncthreads();

        #pragma unroll
        for (int ks = 0; ks < 4; ks++) {
            const int kk = ks * 8;
            uint32_t a[2][4];
            #pragma unroll
            for (int mt = 0; mt < 2; mt++) {
                const int rr = wm + mt * 16;
                a[mt][0] = __float_as_uint(Qs[rr + g    ][kk + tg    ]);
                a[mt][1] = __float_as_uint(Qs[rr + g + 8][kk + tg    ]);
                a[mt][2] = __float_as_uint(Qs[rr + g    ][kk + tg + 4]);
                a[mt][3] = __float_as_uint(Qs[rr + g + 8][kk + tg + 4]);
            }
            #pragma unroll
            for (int nt = 0; nt < 8; nt++) {
                uint32_t bfr[2];
                bfr[0] = __float_as_uint(Ks[wn + nt * 8 + g][kk + tg    ]);
                bfr[1] = __float_as_uint(Ks[wn + nt * 8 + g][kk + tg + 4]);
                mma8(acc[0][nt], a[0], bfr);
                mma8(acc[1][nt], a[1], bfr);
            }
        }
    }

    const float scale = 0.08838834764831845f;   // 1/sqrt(128)
    float* Sb = g_S + (size_t)b * TT * TT;
    #pragma unroll
    for (int mt = 0; mt < 2; mt++) {
        #pragma unroll
        for (int nt = 0; nt < 8; nt++) {
            const int t  = t0 + wm + mt * 16 + g;
            const int sc = s0 + wn + nt * 8 + tg * 2;
            float v0 = (sc     > t) ? NEG_INF : acc[mt][nt][0] * scale;
            float v1 = (sc + 1 > t) ? NEG_INF : acc[mt][nt][1] * scale;
            *(float2*)(Sb + (size_t)t * TT + sc) = make_float2(v0, v1);
            const int t2 = t + 8;
            float v2 = (sc     > t2) ? NEG_INF : acc[mt][nt][2] * scale;
            float v3 = (sc + 1 > t2) ? NEG_INF : acc[mt][nt][3] * scale;
            *(float2*)(Sb + (size_t)t2 * TT + sc) = make_float2(v2, v3);
        }
    }
}

// ============================================================================
// Kernel 3a: per-tile column stats partials (128x128 lower-tri tiles)
// ============================================================================
__global__ __launch_bounds__(128) void stats_part()
{
    const int st = blockIdx.x, tt = blockIdx.y;
    if (tt < st) return;
    const int b = blockIdx.z;

    const int s = st * 128 + threadIdx.x;
    const float* col = g_S + (size_t)b * TT * TT + (size_t)(tt * 128) * TT + s;

    float m = NEG_INF;
    #pragma unroll 8
    for (int t = 0; t < 128; t++)
        m = fmaxf(m, col[(size_t)t * TT]);

    float l = 0.0f;
    #pragma unroll 8
    for (int t = 0; t < 128; t++)
        l += __expf(col[(size_t)t * TT] - m);

    const int o = (b * 16 + tt) * TT + s;
    g_pm[o] = m;
    g_pl[o] = l;
}

// ============================================================================
// Kernel 3b: combine partials -> m, 1/l per column
// ============================================================================
__global__ __launch_bounds__(128) void stats_comb()
{
    const int b = blockIdx.y;
    const int s = blockIdx.x * 128 + threadIdx.x;
    const int st = s >> 7;

    float m = NEG_INF;
    #pragma unroll
    for (int tt = 15; tt >= 0; tt--) {
        if (tt < st) break;
        m = fmaxf(m, g_pm[(b * 16 + tt) * TT + s]);
    }
    float l = 0.0f;
    #pragma unroll
    for (int tt = 15; tt >= 0; tt--) {
        if (tt < st) break;
        const int o = (b * 16 + tt) * TT + s;
        l += g_pl[o] * __expf(g_pm[o] - m);
    }

    g_m[b * TT + s] = m;
    g_r[b * TT + s] = 1.0f / l;
}

// ============================================================================
// Kernel 4: Z = A*V via mma.sync tf32 with register prefetch.
// A = tf32r(exp(S-m)*r) built in the load path; B = g_Vt (K-major in s).
// BM=64 (t), BN=128 (d), BK=32 (s). grid=(32, 4) heavy-first, nk=2(bx+1).
// ============================================================================
__global__ __launch_bounds__(256) void out_kernel(float* __restrict__ out)
{
    __shared__ float As[64][PAD];
    __shared__ float Vs[128][PAD];

    const int b  = blockIdx.y;
    const int bx = gridDim.x - 1 - blockIdx.x;   // heavy tiles first
    const int t0 = bx * 64;
    const int bT = b * TT;

    const float* Sb = g_S + (size_t)b * TT * TT;
    const float* mb = g_m + bT;
    const float* rb = g_r + bT;

    const int tid = threadIdx.x, wid = tid >> 5, lane = tid & 31;
    const int g = lane >> 2, tg = lane & 3;
    const int wm = (wid & 3) * 16;
    const int wn = (wid >> 2) * 64;

    const int lr = tid >> 3, lc = (tid & 7) * 4;   // 32-row stride pattern

    float acc[8][4] = {};
    float4 sv[2], vv[4];

    const int nk = 2 * (bx + 1);

    // preload chunk 0
    #pragma unroll
    for (int j = 0; j < 2; j++)
        sv[j] = *(const float4*)(Sb + (size_t)(t0 + lr + j * 32) * TT + lc);
    #pragma unroll
    for (int j = 0; j < 4; j++)
        vv[j] = *(const float4*)(&g_Vt[lr + j * 32][bT + lc]);

    for (int kt = 0; kt < nk; kt++) {
        const int s0 = kt * 32;
        __syncthreads();
        #pragma unroll
        for (int j = 0; j < 2; j++) {
            float4 v = sv[j];
            const float m0f = mb[s0 + lc], m1f = mb[s0 + lc + 1], m2f = mb[s0 + lc + 2], m3f = mb[s0 + lc + 3];
            const float r0f = rb[s0 + lc], r1f = rb[s0 + lc + 1], r2f = rb[s0 + lc + 2], r3f = rb[s0 + lc + 3];
            As[lr + j * 32][lc    ] = tf32r(__expf(v.x - m0f) * r0f);
            As[lr + j * 32][lc + 1] = tf32r(__expf(v.y - m1f) * r1f);
            As[lr + j * 32][lc + 2] = tf32r(__expf(v.z - m2f) * r2f);
            As[lr + j * 32][lc + 3] = tf32r(__expf(v.w - m3f) * r3f);
        }
        #pragma unroll
        for (int j = 0; j < 4; j++)
            *(float4*)&Vs[lr + j * 32][lc] = vv[j];
        __syncthreads();

        if (kt < nk - 1) {
            const int sn = (kt + 1) * 32;
            #pragma unroll
            for (int j = 0; j < 2; j++)
                sv[j] = *(const float4*)(Sb + (size_t)(t0 + lr + j * 32) * TT + sn + lc);
            #pragma unroll
            for (int j = 0; j < 4; j++)
                vv[j] = *(const float4*)(&g_Vt[lr + j * 32][bT + sn + lc]);
        }

        #pragma unroll
        for (int ks = 0; ks < 4; ks++) {
            const int kk = ks * 8;
            uint32_t a[4];
            a[0] = __float_as_uint(As[wm + g    ][kk + tg    ]);
            a[1] = __float_as_uint(As[wm + g + 8][kk + tg    ]);
            a[2] = __float_as_uint(As[wm + g    ][kk + tg + 4]);
            a[3] = __float_as_uint(As[wm + g + 8][kk + tg + 4]);
            #pragma unroll
            for (int nt = 0; nt < 8; nt++) {
                uint32_t bfr[2];
                bfr[0] = __float_as_uint(Vs[wn + nt * 8 + g][kk + tg    ]);
                bfr[1] = __float_as_uint(Vs[wn + nt * 8 + g][kk + tg + 4]);
                mma8(acc[nt], a, bfr);
            }
        }
    }

    #pragma unroll
    for (int nt = 0; nt < 8; nt++) {
        const int col = wn + nt * 8 + tg * 2;
        *(float2*)(out + (size_t)(bT + t0 + wm + g    ) * DD + col) = make_float2(acc[nt][0], acc[nt][1]);
        *(float2*)(out + (size_t)(bT + t0 + wm + g + 8) * DD + col) = make_float2(acc[nt][2], acc[nt][3]);
    }
}

// ============================================================================
extern "C" void kernel_launch(void* const* d_in, const int* in_sizes, int n_in,
                              void* d_out, int out_size)
{
    const float* x  = (const float*)d_in[0];
    const float* Wq = (const float*)d_in[1];
    const float* Wk = (const float*)d_in[2];
    const float* Wv = (const float*)d_in[3];
    float* out = (float*)d_out;

    prep_w<<<dim3(EE / 32, DD / 32, 3), 256>>>(Wq, Wk, Wv);
    proj_kernel<<<dim3(BB * TT / 64, 3), 256>>>(x);
    score_kernel<<<dim3(TT / 128, TT / 128, BB), 256>>>();
    stats_part<<<dim3(16, 16, BB), 128>>>();
    stats_comb<<<dim3(16, BB), 128>>>();
    out_kernel<<<dim3(TT / 64, BB), 256>>>(out);
}

// round 12
// speedup vs baseline: 2.9199x; 1.0647x over previous
#include <cuda_runtime.h>
#include <cstdint>

#define BB 4
#define TT 2048
#define EE 2048
#define DD 128
#define NEG_INF __int_as_float(0xff800000)
#define PAD 36   // smem row stride (floats): %4==0 for float4, 36%32=4 -> conflict-free frags

#define PROJ_SMEM  (2 * (64 + 128) * PAD * 4)
#define SCORE_SMEM (2 * (128 + 128) * PAD * 4)
#define OUT_SMEM   (2 * (64 + 128) * PAD * 4)

// -------- scratch (device globals: allocation-guard safe) --------
__device__ float g_Wt[3][DD][EE];             // W transposed, tf32-rounded
__device__ float g_Q[BB * TT * DD];           // tf32-rounded
__device__ float g_K[BB * TT * DD];           // tf32-rounded
__device__ float g_Vt[DD][BB * TT];           // V transposed, tf32-rounded
__device__ float g_S[(size_t)BB * TT * TT];
__device__ float g_pm[BB * 32 * TT];          // per-half-tile column max partials
__device__ float g_pl[BB * 32 * TT];          // per-half-tile column sumexp partials
__device__ float g_m[BB * TT];
__device__ float g_r[BB * TT];

__device__ __forceinline__ float tf32r(float x) {
    uint32_t u;
    asm("cvt.rna.tf32.f32 %0, %1;" : "=r"(u) : "f"(x));
    return __uint_as_float(u);
}

// m16n8k8 tf32 MMA: D = A(16x8,row) * B(8x8,col) + C, fp32 accum.
__device__ __forceinline__ void mma8(float* d, const uint32_t* a, const uint32_t* b) {
    asm volatile(
        "mma.sync.aligned.m16n8k8.row.col.f32.tf32.tf32.f32 "
        "{%0,%1,%2,%3}, {%4,%5,%6,%7}, {%8,%9}, {%0,%1,%2,%3};\n"
        : "+f"(d[0]), "+f"(d[1]), "+f"(d[2]), "+f"(d[3])
        : "r"(a[0]), "r"(a[1]), "r"(a[2]), "r"(a[3]), "r"(b[0]), "r"(b[1]));
}

// ============================================================================
// Kernel 0: transpose + tf32-round W -> Wt[w][d][e]
// ============================================================================
__global__ __launch_bounds__(256) void prep_w(
    const float* __restrict__ Wq, const float* __restrict__ Wk, const float* __restrict__ Wv)
{
    __shared__ float t[32][33];
    const int w  = blockIdx.z;
    const float* W = (w == 0) ? Wq : (w == 1) ? Wk : Wv;
    const int e0 = blockIdx.x * 32, d0 = blockIdx.y * 32;
    const int tx = threadIdx.x & 31, ty = threadIdx.x >> 5;
    for (int i = ty; i < 32; i += 8)
        t[i][tx] = W[(size_t)(e0 + i) * DD + d0 + tx];
    __syncthreads();
    for (int i = ty; i < 32; i += 8)
        g_Wt[w][d0 + i][e0 + tx] = tf32r(t[tx][i]);
}

// ============================================================================
// Kernel 1: projection via mma.sync tf32, double-buffered smem, 1 barrier/chunk.
// C[64,128] = X[64,2048] @ Wt^T. grid=(128, 3), 256 thr, warp tile 16x64, BK=32.
// ============================================================================
__global__ __launch_bounds__(256) void proj_kernel(const float* __restrict__ x)
{
    extern __shared__ float dsm[];
    float* Xs = dsm;                      // [2][64][PAD]
    float* Ws = dsm + 2 * 64 * PAD;       // [2][128][PAD]

    const int m0 = blockIdx.x * 64;
    const int w  = blockIdx.y;
    const float* Wt = &g_Wt[w][0][0];

    const int tid = threadIdx.x, wid = tid >> 5, lane = tid & 31;
    const int g = lane >> 2, tg = lane & 3;
    const int wm = (wid & 3) * 16;
    const int wn = (wid >> 2) * 64;

    const int xr = tid >> 3, xc = (tid & 7) * 4;
    float acc[8][4] = {};
    float4 xv[2], wv[4];

    // preload chunk 0
    #pragma unroll
    for (int j = 0; j < 2; j++)
        xv[j] = *(const float4*)(x + (size_t)(m0 + xr + j * 32) * EE + xc);
    #pragma unroll
    for (int j = 0; j < 4; j++)
        wv[j] = *(const float4*)(Wt + (size_t)(xr + j * 32) * EE + xc);

    for (int i = 0; i < 64; i++) {
        const int xb = (i & 1) * 64, wb = (i & 1) * 128;

        #pragma unroll
        for (int j = 0; j < 2; j++) {
            float4 v = xv[j];
            v.x = tf32r(v.x); v.y = tf32r(v.y); v.z = tf32r(v.z); v.w = tf32r(v.w);
            *(float4*)&Xs[(xb + xr + j * 32) * PAD + xc] = v;
        }
        #pragma unroll
        for (int j = 0; j < 4; j++)
            *(float4*)&Ws[(wb + xr + j * 32) * PAD + xc] = wv[j];

        if (i < 63) {
            const int k0 = (i + 1) * 32;
            #pragma unroll
            for (int j = 0; j < 2; j++)
                xv[j] = *(const float4*)(x + (size_t)(m0 + xr + j * 32) * EE + k0 + xc);
            #pragma unroll
            for (int j = 0; j < 4; j++)
                wv[j] = *(const float4*)(Wt + (size_t)(xr + j * 32) * EE + k0 + xc);
        }
        __syncthreads();

        #pragma unroll
        for (int ks = 0; ks < 4; ks++) {
            const int kk = ks * 8;
            uint32_t a[4];
            a[0] = __float_as_uint(Xs[(xb + wm + g    ) * PAD + kk + tg    ]);
            a[1] = __float_as_uint(Xs[(xb + wm + g + 8) * PAD + kk + tg    ]);
            a[2] = __float_as_uint(Xs[(xb + wm + g    ) * PAD + kk + tg + 4]);
            a[3] = __float_as_uint(Xs[(xb + wm + g + 8) * PAD + kk + tg + 4]);
            #pragma unroll
            for (int nt = 0; nt < 8; nt++) {
                uint32_t b[2];
                b[0] = __float_as_uint(Ws[(wb + wn + nt * 8 + g) * PAD + kk + tg    ]);
                b[1] = __float_as_uint(Ws[(wb + wn + nt * 8 + g) * PAD + kk + tg + 4]);
                mma8(acc[nt], a, b);
            }
        }
    }

    if (w < 2) {
        float* out = (w == 0) ? g_Q : g_K;
        #pragma unroll
        for (int nt = 0; nt < 8; nt++) {
            const int col = wn + nt * 8 + tg * 2;
            *(float2*)(out + (size_t)(m0 + wm + g    ) * DD + col) =
                make_float2(tf32r(acc[nt][0]), tf32r(acc[nt][1]));
            *(float2*)(out + (size_t)(m0 + wm + g + 8) * DD + col) =
                make_float2(tf32r(acc[nt][2]), tf32r(acc[nt][3]));
        }
    } else {
        #pragma unroll
        for (int nt = 0; nt < 8; nt++) {
            const int col = wn + nt * 8 + tg * 2;
            g_Vt[col    ][m0 + wm + g    ] = tf32r(acc[nt][0]);
            g_Vt[col + 1][m0 + wm + g    ] = tf32r(acc[nt][1]);
            g_Vt[col    ][m0 + wm + g + 8] = tf32r(acc[nt][2]);
            g_Vt[col + 1][m0 + wm + g + 8] = tf32r(acc[nt][3]);
        }
    }
}

// ============================================================================
// Kernel 2: S = scale*QK^T (causal), mma.sync tf32, double-buffered, lower-tri.
// Q/K already tf32-rounded -> pure copy loads.
// ============================================================================
__global__ __launch_bounds__(256) void score_kernel()
{
    extern __shared__ float dsm[];
    float* Qs = dsm;                      // [2][128][PAD]
    float* Ks = dsm + 2 * 128 * PAD;      // [2][128][PAD]

    const int bt = blockIdx.x, bs = blockIdx.y;
    if (bs > bt) return;
    const int b = blockIdx.z;

    const float* Q = g_Q + (size_t)b * TT * DD;
    const float* K = g_K + (size_t)b * TT * DD;
    const int t0 = bt * 128, s0 = bs * 128;

    const int tid = threadIdx.x, wid = tid >> 5, lane = tid & 31;
    const int g = lane >> 2, tg = lane & 3;
    const int wm = (wid & 3) * 32;
    const int wn = (wid >> 2) * 64;

    const int lr = tid >> 3, lc = (tid & 7) * 4;   // + j*32 rows
    float acc[2][8][4] = {};
    float4 qv[4], kv[4];

    #pragma unroll
    for (int j = 0; j < 4; j++) {
        qv[j] = *(const float4*)(Q + (size_t)(t0 + lr + j * 32) * DD + lc);
        kv[j] = *(const float4*)(K + (size_t)(s0 + lr + j * 32) * DD + lc);
    }

    for (int i = 0; i < 4; i++) {
        const int qb = (i & 1) * 128;

        #pragma unroll
        for (int j = 0; j < 4; j++) {
            *(float4*)&Qs[(qb + lr + j * 32) * PAD + lc] = qv[j];
            *(float4*)&Ks[(qb + lr + j * 32) * PAD + lc] = kv[j];
        }

        if (i < 3) {
            const int k0 = (i + 1) * 32;
            #pragma unroll
            for (int j = 0; j < 4; j++) {
                qv[j] = *(const float4*)(Q + (size_t)(t0 + lr + j * 32) * DD + k0 + lc);
                kv[j] = *(const float4*)(K + (size_t)(s0 + lr + j * 32) * DD + k0 + lc);
            }
        }
        __syncthreads();

        #pragma unroll
        for (int ks = 0; ks < 4; ks++) {
            const int kk = ks * 8;
            uint32_t a[2][4];
            #pragma unroll
            for (int mt = 0; mt < 2; mt++) {
                const int rr = qb + wm + mt * 16;
                a[mt][0] = __float_as_uint(Qs[(rr + g    ) * PAD + kk + tg    ]);
                a[mt][1] = __float_as_uint(Qs[(rr + g + 8) * PAD + kk + tg    ]);
                a[mt][2] = __float_as_uint(Qs[(rr + g    ) * PAD + kk + tg + 4]);
                a[mt][3] = __float_as_uint(Qs[(rr + g + 8) * PAD + kk + tg + 4]);
            }
            #pragma unroll
            for (int nt = 0; nt < 8; nt++) {
                uint32_t bfr[2];
                bfr[0] = __float_as_uint(Ks[(qb + wn + nt * 8 + g) * PAD + kk + tg    ]);
                bfr[1] = __float_as_uint(Ks[(qb + wn + nt * 8 + g) * PAD + kk + tg + 4]);
                mma8(acc[0][nt], a[0], bfr);
                mma8(acc[1][nt], a[1], bfr);
            }
        }
    }

    const float scale = 0.08838834764831845f;   // 1/sqrt(128)
    float* Sb = g_S + (size_t)b * TT * TT;
    #pragma unroll
    for (int mt = 0; mt < 2; mt++) {
        #pragma unroll
        for (int nt = 0; nt < 8; nt++) {
            const int t  = t0 + wm + mt * 16 + g;
            const int sc = s0 + wn + nt * 8 + tg * 2;
            float v0 = (sc     > t) ? NEG_INF : acc[mt][nt][0] * scale;
            float v1 = (sc + 1 > t) ? NEG_INF : acc[mt][nt][1] * scale;
            *(float2*)(Sb + (size_t)t * TT + sc) = make_float2(v0, v1);
            const int t2 = t + 8;
            float v2 = (sc     > t2) ? NEG_INF : acc[mt][nt][2] * scale;
            float v3 = (sc + 1 > t2) ? NEG_INF : acc[mt][nt][3] * scale;
            *(float2*)(Sb + (size_t)t2 * TT + sc) = make_float2(v2, v3);
        }
    }
}

// ============================================================================
// Kernel 3a: per-half-tile column stats partials (64 rows x 128 cols).
// grid=(16 s-tiles, 32 t-half-tiles, 4). Active iff tt >= 2*st.
// ============================================================================
__global__ __launch_bounds__(128) void stats_part()
{
    const int st = blockIdx.x, tt = blockIdx.y;
    if (tt < 2 * st) return;
    const int b = blockIdx.z;

    const int s = st * 128 + threadIdx.x;
    const float* col = g_S + (size_t)b * TT * TT + (size_t)(tt * 64) * TT + s;

    float m = NEG_INF;
    #pragma unroll 8
    for (int t = 0; t < 64; t++)
        m = fmaxf(m, col[(size_t)t * TT]);

    const float mm = (m == NEG_INF) ? 0.0f : m;   // avoid exp(-inf - -inf)=NaN
    float l = 0.0f;
    #pragma unroll 8
    for (int t = 0; t < 64; t++)
        l += __expf(col[(size_t)t * TT] - mm);

    const int o = (b * 32 + tt) * TT + s;
    g_pm[o] = m;
    g_pl[o] = l;
}

// ============================================================================
// Kernel 3b: combine partials -> m, 1/l per column. grid=(16,4), 128 threads.
// ============================================================================
__global__ __launch_bounds__(128) void stats_comb()
{
    const int b = blockIdx.y;
    const int s = blockIdx.x * 128 + threadIdx.x;
    const int st = blockIdx.x;

    float m = NEG_INF;
    for (int tt = 31; tt >= 2 * st; tt--)
        m = fmaxf(m, g_pm[(b * 32 + tt) * TT + s]);
    float l = 0.0f;
    for (int tt = 31; tt >= 2 * st; tt--) {
        const int o = (b * 32 + tt) * TT + s;
        l += g_pl[o] * __expf(g_pm[o] - m);       // g_pm=-inf -> exp=0, g_pl=0
    }

    g_m[b * TT + s] = m;
    g_r[b * TT + s] = 1.0f / l;
}

// ============================================================================
// Kernel 4: Z = A*V via mma.sync tf32, double-buffered, heavy-first.
// A = tf32r(exp(S-m)*r) built in the store path; B = g_Vt (K-major in s).
// BM=64 (t), BN=128 (d), BK=32 (s). grid=(32, 4), nk=2(bx+1).
// ============================================================================
__global__ __launch_bounds__(256) void out_kernel(float* __restrict__ out)
{
    extern __shared__ float dsm[];
    float* As = dsm;                      // [2][64][PAD]
    float* Vs = dsm + 2 * 64 * PAD;       // [2][128][PAD]

    const int b  = blockIdx.y;
    const int bx = gridDim.x - 1 - blockIdx.x;   // heavy tiles first
    const int t0 = bx * 64;
    const int bT = b * TT;

    const float* Sb = g_S + (size_t)b * TT * TT;
    const float* mb = g_m + bT;
    const float* rb = g_r + bT;

    const int tid = threadIdx.x, wid = tid >> 5, lane = tid & 31;
    const int g = lane >> 2, tg = lane & 3;
    const int wm = (wid & 3) * 16;
    const int wn = (wid >> 2) * 64;

    const int lr = tid >> 3, lc = (tid & 7) * 4;

    float acc[8][4] = {};
    float4 sv[2], vv[4];

    const int nk = 2 * (bx + 1);

    #pragma unroll
    for (int j = 0; j < 2; j++)
        sv[j] = *(const float4*)(Sb + (size_t)(t0 + lr + j * 32) * TT + lc);
    #pragma unroll
    for (int j = 0; j < 4; j++)
        vv[j] = *(const float4*)(&g_Vt[lr + j * 32][bT + lc]);

    for (int kt = 0; kt < nk; kt++) {
        const int s0 = kt * 32;
        const int ab = (kt & 1) * 64, vb = (kt & 1) * 128;

        #pragma unroll
        for (int j = 0; j < 2; j++) {
            float4 v = sv[j];
            const float m0f = mb[s0 + lc], m1f = mb[s0 + lc + 1], m2f = mb[s0 + lc + 2], m3f = mb[s0 + lc + 3];
            const float r0f = rb[s0 + lc], r1f = rb[s0 + lc + 1], r2f = rb[s0 + lc + 2], r3f = rb[s0 + lc + 3];
            float* row = &As[(ab + lr + j * 32) * PAD];
            row[lc    ] = tf32r(__expf(v.x - m0f) * r0f);
            row[lc + 1] = tf32r(__expf(v.y - m1f) * r1f);
            row[lc + 2] = tf32r(__expf(v.z - m2f) * r2f);
            row[lc + 3] = tf32r(__expf(v.w - m3f) * r3f);
        }
        #pragma unroll
        for (int j = 0; j < 4; j++)
            *(float4*)&Vs[(vb + lr + j * 32) * PAD + lc] = vv[j];

        if (kt < nk - 1) {
            const int sn = (kt + 1) * 32;
            #pragma unroll
            for (int j = 0; j < 2; j++)
                sv[j] = *(const float4*)(Sb + (size_t)(t0 + lr + j * 32) * TT + sn + lc);
            #pragma unroll
            for (int j = 0; j < 4; j++)
                vv[j] = *(const float4*)(&g_Vt[lr + j * 32][bT + sn + lc]);
        }
        __syncthreads();

        #pragma unroll
        for (int ks = 0; ks < 4; ks++) {
            const int kk = ks * 8;
            uint32_t a[4];
            a[0] = __float_as_uint(As[(ab + wm + g    ) * PAD + kk + tg    ]);
            a[1] = __float_as_uint(As[(ab + wm + g + 8) * PAD + kk + tg    ]);
            a[2] = __float_as_uint(As[(ab + wm + g    ) * PAD + kk + tg + 4]);
            a[3] = __float_as_uint(As[(ab + wm + g + 8) * PAD + kk + tg + 4]);
            #pragma unroll
            for (int nt = 0; nt < 8; nt++) {
                uint32_t bfr[2];
                bfr[0] = __float_as_uint(Vs[(vb + wn + nt * 8 + g) * PAD + kk + tg    ]);
                bfr[1] = __float_as_uint(Vs[(vb + wn + nt * 8 + g) * PAD + kk + tg + 4]);
                mma8(acc[nt], a, bfr);
            }
        }
    }

    #pragma unroll
    for (int nt = 0; nt < 8; nt++) {
        const int col = wn + nt * 8 + tg * 2;
        *(float2*)(out + (size_t)(bT + t0 + wm + g    ) * DD + col) = make_float2(acc[nt][0], acc[nt][1]);
        *(float2*)(out + (size_t)(bT + t0 + wm + g + 8) * DD + col) = make_float2(acc[nt][2], acc[nt][3]);
    }
}

// ============================================================================
extern "C" void kernel_launch(void* const* d_in, const int* in_sizes, int n_in,
                              void* d_out, int out_size)
{
    const float* x  = (const float*)d_in[0];
    const float* Wq = (const float*)d_in[1];
    const float* Wk = (const float*)d_in[2];
    const float* Wv = (const float*)d_in[3];
    float* out = (float*)d_out;

    static int attr_done = 0;
    if (!attr_done) {
        cudaFuncSetAttribute(proj_kernel,  cudaFuncAttributeMaxDynamicSharedMemorySize, PROJ_SMEM);
        cudaFuncSetAttribute(score_kernel, cudaFuncAttributeMaxDynamicSharedMemorySize, SCORE_SMEM);
        cudaFuncSetAttribute(out_kernel,   cudaFuncAttributeMaxDynamicSharedMemorySize, OUT_SMEM);
        attr_done = 1;
    }

    prep_w<<<dim3(EE / 32, DD / 32, 3), 256>>>(Wq, Wk, Wv);
    proj_kernel<<<dim3(BB * TT / 64, 3), 256, PROJ_SMEM>>>(x);
    score_kernel<<<dim3(TT / 128, TT / 128, BB), 256, SCORE_SMEM>>>();
    stats_part<<<dim3(16, 32, BB), 128>>>();
    stats_comb<<<dim3(16, BB), 128>>>();
    out_kernel<<<dim3(TT / 64, BB), 256, OUT_SMEM>>>(out);
}

// round 13
// speedup vs baseline: 3.7676x; 1.2903x over previous
#include <cuda_runtime.h>
#include <cuda_fp16.h>
#include <cstdint>

#define BB 4
#define TT 2048
#define EE 2048
#define DD 128
#define NEG_INF __int_as_float(0xff800000)
#define HPAD 40   // half-row stride: word bank = 20*row + tg mod 32 -> conflict-free

// -------- scratch (device globals: allocation-guard safe) --------
__device__ __half g_Wth[3][DD][EE];           // W transposed, fp16
__device__ __half g_Qh[BB * TT * DD];         // fp16
__device__ __half g_Kh[BB * TT * DD];         // fp16
__device__ __half g_Vth[DD][BB * TT];         // V transposed, fp16
__device__ float g_S[(size_t)BB * TT * TT];   // fp32 (exponent precision)
__device__ float g_pm[BB * 32 * TT];
__device__ float g_pl[BB * 32 * TT];
__device__ float g_m[BB * TT];
__device__ float g_r[BB * TT];

// m16n8k16 fp16 MMA: D = A(16x16,row) * B(16x8,col) + C, fp32 accum.
__device__ __forceinline__ void mma16(float* d, const uint32_t* a, const uint32_t* b) {
    asm volatile(
        "mma.sync.aligned.m16n8k16.row.col.f32.f16.f16.f32 "
        "{%0,%1,%2,%3}, {%4,%5,%6,%7}, {%8,%9}, {%0,%1,%2,%3};\n"
        : "+f"(d[0]), "+f"(d[1]), "+f"(d[2]), "+f"(d[3])
        : "r"(a[0]), "r"(a[1]), "r"(a[2]), "r"(a[3]), "r"(b[0]), "r"(b[1]));
}

__device__ __forceinline__ uint32_t lds32(const __half* p) {
    return *(const uint32_t*)p;
}

// ============================================================================
// Kernel 0: transpose + fp16-round W -> Wth[w][d][e]
// ============================================================================
__global__ __launch_bounds__(256) void prep_w(
    const float* __restrict__ Wq, const float* __restrict__ Wk, const float* __restrict__ Wv)
{
    __shared__ float t[32][33];
    const int w  = blockIdx.z;
    const float* W = (w == 0) ? Wq : (w == 1) ? Wk : Wv;
    const int e0 = blockIdx.x * 32, d0 = blockIdx.y * 32;
    const int tx = threadIdx.x & 31, ty = threadIdx.x >> 5;
    for (int i = ty; i < 32; i += 8)
        t[i][tx] = W[(size_t)(e0 + i) * DD + d0 + tx];
    __syncthreads();
    for (int i = ty; i < 32; i += 8)
        g_Wth[w][d0 + i][e0 + tx] = __float2half_rn(t[tx][i]);
}

// ============================================================================
// Kernel 1: projection via mma.sync fp16, double-buffered, reg prefetch.
// C[64,128] = X[64,2048] @ Wth^T. grid=(128, 3), 256 thr, warp tile 16x64, BK=32.
// ============================================================================
__global__ __launch_bounds__(256) void proj_kernel(const float* __restrict__ x)
{
    __shared__ __half Xs[2][64][HPAD];
    __shared__ __half Ws[2][128][HPAD];

    const int m0 = blockIdx.x * 64;
    const int w  = blockIdx.y;
    const __half* Wt = &g_Wth[w][0][0];

    const int tid = threadIdx.x, wid = tid >> 5, lane = tid & 31;
    const int g = lane >> 2, tg = lane & 3;
    const int wm = (wid & 3) * 16;
    const int wn = (wid >> 2) * 64;

    // X: 64 rows x 32 halfs, 1 slot/thread: row=tid>>2, c8=(tid&3)*8
    const int xr = tid >> 2, xc8 = (tid & 3) * 8;
    // W: 128 rows x 32 halfs, 2 slots/thread
    const int wr0 = tid >> 2, wr1 = (tid + 256) >> 2;

    float acc[8][4] = {};
    float4 xa, xb2;
    uint4 wv[2];

    // preload chunk 0
    xa  = *(const float4*)(x + (size_t)(m0 + xr) * EE + xc8);
    xb2 = *(const float4*)(x + (size_t)(m0 + xr) * EE + xc8 + 4);
    wv[0] = *(const uint4*)(Wt + (size_t)wr0 * EE + xc8);
    wv[1] = *(const uint4*)(Wt + (size_t)wr1 * EE + xc8);

    for (int i = 0; i < 64; i++) {
        const int p = i & 1;

        {
            __half2 h0 = __floats2half2_rn(xa.x, xa.y);
            __half2 h1 = __floats2half2_rn(xa.z, xa.w);
            __half2 h2 = __floats2half2_rn(xb2.x, xb2.y);
            __half2 h3 = __floats2half2_rn(xb2.z, xb2.w);
            __half2* d = (__half2*)&Xs[p][xr][xc8];
            d[0] = h0; d[1] = h1; d[2] = h2; d[3] = h3;
        }
        *(uint4*)&Ws[p][wr0][xc8] = wv[0];
        *(uint4*)&Ws[p][wr1][xc8] = wv[1];

        if (i < 63) {
            const int k0 = (i + 1) * 32;
            xa  = *(const float4*)(x + (size_t)(m0 + xr) * EE + k0 + xc8);
            xb2 = *(const float4*)(x + (size_t)(m0 + xr) * EE + k0 + xc8 + 4);
            wv[0] = *(const uint4*)(Wt + (size_t)wr0 * EE + k0 + xc8);
            wv[1] = *(const uint4*)(Wt + (size_t)wr1 * EE + k0 + xc8);
        }
        __syncthreads();

        #pragma unroll
        for (int ks = 0; ks < 2; ks++) {
            const int kk = ks * 16;
            uint32_t a[4];
            a[0] = lds32(&Xs[p][wm + g    ][kk + 2 * tg    ]);
            a[1] = lds32(&Xs[p][wm + g + 8][kk + 2 * tg    ]);
            a[2] = lds32(&Xs[p][wm + g    ][kk + 2 * tg + 8]);
            a[3] = lds32(&Xs[p][wm + g + 8][kk + 2 * tg + 8]);
            #pragma unroll
            for (int nt = 0; nt < 8; nt++) {
                uint32_t b[2];
                b[0] = lds32(&Ws[p][wn + nt * 8 + g][kk + 2 * tg    ]);
                b[1] = lds32(&Ws[p][wn + nt * 8 + g][kk + 2 * tg + 8]);
                mma16(acc[nt], a, b);
            }
        }
        __syncthreads();
    }

    if (w < 2) {
        __half* out = (w == 0) ? g_Qh : g_Kh;
        #pragma unroll
        for (int nt = 0; nt < 8; nt++) {
            const int col = wn + nt * 8 + tg * 2;
            *(__half2*)(out + (size_t)(m0 + wm + g    ) * DD + col) =
                __floats2half2_rn(acc[nt][0], acc[nt][1]);
            *(__half2*)(out + (size_t)(m0 + wm + g + 8) * DD + col) =
                __floats2half2_rn(acc[nt][2], acc[nt][3]);
        }
    } else {
        #pragma unroll
        for (int nt = 0; nt < 8; nt++) {
            const int col = wn + nt * 8 + tg * 2;
            g_Vth[col    ][m0 + wm + g    ] = __float2half_rn(acc[nt][0]);
            g_Vth[col + 1][m0 + wm + g    ] = __float2half_rn(acc[nt][1]);
            g_Vth[col    ][m0 + wm + g + 8] = __float2half_rn(acc[nt][2]);
            g_Vth[col + 1][m0 + wm + g + 8] = __float2half_rn(acc[nt][3]);
        }
    }
}

// ============================================================================
// Kernel 2: S = scale*QK^T (causal), mma.sync fp16, double-buffered, lower-tri.
// ============================================================================
__global__ __launch_bounds__(256) void score_kernel()
{
    __shared__ __half Qs[2][128][HPAD];
    __shared__ __half Ks[2][128][HPAD];

    const int bt = blockIdx.x, bs = blockIdx.y;
    if (bs > bt) return;
    const int b = blockIdx.z;

    const __half* Q = g_Qh + (size_t)b * TT * DD;
    const __half* K = g_Kh + (size_t)b * TT * DD;
    const int t0 = bt * 128, s0 = bs * 128;

    const int tid = threadIdx.x, wid = tid >> 5, lane = tid & 31;
    const int g = lane >> 2, tg = lane & 3;
    const int wm = (wid & 3) * 32;
    const int wn = (wid >> 2) * 64;

    // 128 rows x 32 halfs, 2 slots/thread
    const int r0 = tid >> 2, r1 = (tid + 256) >> 2;
    const int c8 = (tid & 3) * 8;

    float acc[2][8][4] = {};
    uint4 qv[2], kv[2];

    qv[0] = *(const uint4*)(Q + (size_t)(t0 + r0) * DD + c8);
    qv[1] = *(const uint4*)(Q + (size_t)(t0 + r1) * DD + c8);
    kv[0] = *(const uint4*)(K + (size_t)(s0 + r0) * DD + c8);
    kv[1] = *(const uint4*)(K + (size_t)(s0 + r1) * DD + c8);

    for (int i = 0; i < 4; i++) {
        const int p = i & 1;

        *(uint4*)&Qs[p][r0][c8] = qv[0];
        *(uint4*)&Qs[p][r1][c8] = qv[1];
        *(uint4*)&Ks[p][r0][c8] = kv[0];
        *(uint4*)&Ks[p][r1][c8] = kv[1];

        if (i < 3) {
            const int k0 = (i + 1) * 32;
            qv[0] = *(const uint4*)(Q + (size_t)(t0 + r0) * DD + k0 + c8);
            qv[1] = *(const uint4*)(Q + (size_t)(t0 + r1) * DD + k0 + c8);
            kv[0] = *(const uint4*)(K + (size_t)(s0 + r0) * DD + k0 + c8);
            kv[1] = *(const uint4*)(K + (size_t)(s0 + r1) * DD + k0 + c8);
        }
        __syncthreads();

        #pragma unroll
        for (int ks = 0; ks < 2; ks++) {
            const int kk = ks * 16;
            uint32_t a[2][4];
            #pragma unroll
            for (int mt = 0; mt < 2; mt++) {
                const int rr = wm + mt * 16;
                a[mt][0] = lds32(&Qs[p][rr + g    ][kk + 2 * tg    ]);
                a[mt][1] = lds32(&Qs[p][rr + g + 8][kk + 2 * tg    ]);
                a[mt][2] = lds32(&Qs[p][rr + g    ][kk + 2 * tg + 8]);
                a[mt][3] = lds32(&Qs[p][rr + g + 8][kk + 2 * tg + 8]);
            }
            #pragma unroll
            for (int nt = 0; nt < 8; nt++) {
                uint32_t bfr[2];
                bfr[0] = lds32(&Ks[p][wn + nt * 8 + g][kk + 2 * tg    ]);
                bfr[1] = lds32(&Ks[p][wn + nt * 8 + g][kk + 2 * tg + 8]);
                mma16(acc[0][nt], a[0], bfr);
                mma16(acc[1][nt], a[1], bfr);
            }
        }
        __syncthreads();
    }

    const float scale = 0.08838834764831845f;   // 1/sqrt(128)
    float* Sb = g_S + (size_t)b * TT * TT;
    #pragma unroll
    for (int mt = 0; mt < 2; mt++) {
        #pragma unroll
        for (int nt = 0; nt < 8; nt++) {
            const int t  = t0 + wm + mt * 16 + g;
            const int sc = s0 + wn + nt * 8 + tg * 2;
            float v0 = (sc     > t) ? NEG_INF : acc[mt][nt][0] * scale;
            float v1 = (sc + 1 > t) ? NEG_INF : acc[mt][nt][1] * scale;
            *(float2*)(Sb + (size_t)t * TT + sc) = make_float2(v0, v1);
            const int t2 = t + 8;
            float v2 = (sc     > t2) ? NEG_INF : acc[mt][nt][2] * scale;
            float v3 = (sc + 1 > t2) ? NEG_INF : acc[mt][nt][3] * scale;
            *(float2*)(Sb + (size_t)t2 * TT + sc) = make_float2(v2, v3);
        }
    }
}

// ============================================================================
// Kernel 3a: per-half-tile column stats partials (64 rows x 128 cols).
// grid=(16, 32, 4). Active iff tt >= 2*st.
// ============================================================================
__global__ __launch_bounds__(128) void stats_part()
{
    const int st = blockIdx.x, tt = blockIdx.y;
    if (tt < 2 * st) return;
    const int b = blockIdx.z;

    const int s = st * 128 + threadIdx.x;
    const float* col = g_S + (size_t)b * TT * TT + (size_t)(tt * 64) * TT + s;

    float m = NEG_INF;
    #pragma unroll 8
    for (int t = 0; t < 64; t++)
        m = fmaxf(m, col[(size_t)t * TT]);

    const float mm = (m == NEG_INF) ? 0.0f : m;
    float l = 0.0f;
    #pragma unroll 8
    for (int t = 0; t < 64; t++)
        l += __expf(col[(size_t)t * TT] - mm);

    const int o = (b * 32 + tt) * TT + s;
    g_pm[o] = m;
    g_pl[o] = l;
}

// ============================================================================
// Kernel 3b: combine partials -> m, 1/l per column. grid=(16,4), 128 threads.
// ============================================================================
__global__ __launch_bounds__(128) void stats_comb()
{
    const int b = blockIdx.y;
    const int s = blockIdx.x * 128 + threadIdx.x;
    const int st = blockIdx.x;

    float m = NEG_INF;
    for (int tt = 31; tt >= 2 * st; tt--)
        m = fmaxf(m, g_pm[(b * 32 + tt) * TT + s]);
    float l = 0.0f;
    for (int tt = 31; tt >= 2 * st; tt--) {
        const int o = (b * 32 + tt) * TT + s;
        l += g_pl[o] * __expf(g_pm[o] - m);
    }

    g_m[b * TT + s] = m;
    g_r[b * TT + s] = 1.0f / l;
}

// ============================================================================
// Kernel 4: Z = A*V via mma.sync fp16, double-buffered, heavy-first.
// A = fp16(exp(S-m)*r); B = g_Vth (K-major in s). BM=64, BN=128, BK=32.
// grid=(32, 4), nk=2(bx+1).
// ============================================================================
__global__ __launch_bounds__(256) void out_kernel(float* __restrict__ out)
{
    __shared__ __half As[2][64][HPAD];
    __shared__ __half Vs[2][128][HPAD];

    const int b  = blockIdx.y;
    const int bx = gridDim.x - 1 - blockIdx.x;   // heavy tiles first
    const int t0 = bx * 64;
    const int bT = b * TT;

    const float* Sb = g_S + (size_t)b * TT * TT;
    const float* mb = g_m + bT;
    const float* rb = g_r + bT;

    const int tid = threadIdx.x, wid = tid >> 5, lane = tid & 31;
    const int g = lane >> 2, tg = lane & 3;
    const int wm = (wid & 3) * 16;
    const int wn = (wid >> 2) * 64;

    // A: 64 rows x 32 cols; thread: rows lr, lr+32; cols lc..lc+3
    const int lr = tid >> 3, lc = (tid & 7) * 4;
    // V: 128 rows x 32 halfs, 2 slots/thread
    const int vr0 = tid >> 2, vr1 = (tid + 256) >> 2;
    const int vc8 = (tid & 3) * 8;

    float acc[8][4] = {};
    float4 sv[2];
    uint4 vv[2];

    const int nk = 2 * (bx + 1);

    sv[0] = *(const float4*)(Sb + (size_t)(t0 + lr)      * TT + lc);
    sv[1] = *(const float4*)(Sb + (size_t)(t0 + lr + 32) * TT + lc);
    vv[0] = *(const uint4*)(&g_Vth[vr0][bT + vc8]);
    vv[1] = *(const uint4*)(&g_Vth[vr1][bT + vc8]);

    for (int kt = 0; kt < nk; kt++) {
        const int s0 = kt * 32;
        const int p = kt & 1;

        {
            const float m0f = mb[s0 + lc], m1f = mb[s0 + lc + 1], m2f = mb[s0 + lc + 2], m3f = mb[s0 + lc + 3];
            const float r0f = rb[s0 + lc], r1f = rb[s0 + lc + 1], r2f = rb[s0 + lc + 2], r3f = rb[s0 + lc + 3];
            #pragma unroll
            for (int j = 0; j < 2; j++) {
                float4 v = sv[j];
                __half2* d = (__half2*)&As[p][lr + j * 32][lc];
                d[0] = __floats2half2_rn(__expf(v.x - m0f) * r0f, __expf(v.y - m1f) * r1f);
                d[1] = __floats2half2_rn(__expf(v.z - m2f) * r2f, __expf(v.w - m3f) * r3f);
            }
        }
        *(uint4*)&Vs[p][vr0][vc8] = vv[0];
        *(uint4*)&Vs[p][vr1][vc8] = vv[1];

        if (kt < nk - 1) {
            const int sn = (kt + 1) * 32;
            sv[0] = *(const float4*)(Sb + (size_t)(t0 + lr)      * TT + sn + lc);
            sv[1] = *(const float4*)(Sb + (size_t)(t0 + lr + 32) * TT + sn + lc);
            vv[0] = *(const uint4*)(&g_Vth[vr0][bT + sn + vc8]);
            vv[1] = *(const uint4*)(&g_Vth[vr1][bT + sn + vc8]);
        }
        __syncthreads();

        #pragma unroll
        for (int ks = 0; ks < 2; ks++) {
            const int kk = ks * 16;
            uint32_t a[4];
            a[0] = lds32(&As[p][wm + g    ][kk + 2 * tg    ]);
            a[1] = lds32(&As[p][wm + g + 8][kk + 2 * tg    ]);
            a[2] = lds32(&As[p][wm + g    ][kk + 2 * tg + 8]);
            a[3] = lds32(&As[p][wm + g + 8][kk + 2 * tg + 8]);
            #pragma unroll
            for (int nt = 0; nt < 8; nt++) {
                uint32_t bfr[2];
                bfr[0] = lds32(&Vs[p][wn + nt * 8 + g][kk + 2 * tg    ]);
                bfr[1] = lds32(&Vs[p][wn + nt * 8 + g][kk + 2 * tg + 8]);
                mma16(acc[nt], a, bfr);
            }
        }
        __syncthreads();
    }

    #pragma unroll
    for (int nt = 0; nt < 8; nt++) {
        const int col = wn + nt * 8 + tg * 2;
        *(float2*)(out + (size_t)(bT + t0 + wm + g    ) * DD + col) = make_float2(acc[nt][0], acc[nt][1]);
        *(float2*)(out + (size_t)(bT + t0 + wm + g + 8) * DD + col) = make_float2(acc[nt][2], acc[nt][3]);
    }
}

// ============================================================================
extern "C" void kernel_launch(void* const* d_in, const int* in_sizes, int n_in,
                              void* d_out, int out_size)
{
    const float* x  = (const float*)d_in[0];
    const float* Wq = (const float*)d_in[1];
    const float* Wk = (const float*)d_in[2];
    const float* Wv = (const float*)d_in[3];
    float* out = (float*)d_out;

    prep_w<<<dim3(EE / 32, DD / 32, 3), 256>>>(Wq, Wk, Wv);
    proj_kernel<<<dim3(BB * TT / 64, 3), 256>>>(x);
    score_kernel<<<dim3(TT / 128, TT / 128, BB), 256>>>();
    stats_part<<<dim3(16, 32, BB), 128>>>();
    stats_comb<<<dim3(16, BB), 128>>>();
    out_kernel<<<dim3(TT / 64, BB), 256>>>(out);
}